// round 1
// baseline (speedup 1.0000x reference)
#include <cuda_runtime.h>
#include <cstddef>

#define N_TOK   8192
#define D_IN    384
#define D_H     64
#define N_HEADS 4
#define N_CLS   6
#define LN_EPS  1e-5f

// Scratch (no allocations allowed)
__device__ float g_hp[(size_t)N_HEADS * N_TOK * D_H];   // per-head projected features (V and K)
__device__ float g_ss[(size_t)N_HEADS * N_TOK];         // per-head row sum-of-squares
__device__ float g_hh[(size_t)N_HEADS * N_TOK * D_H];   // per-head attention outputs

// ---------------------------------------------------------------------------
// Kernel 1: h = relu(x@proj_w + proj_b); hp[h] = h@head_w[h] + head_b[h];
//           sumsq[h][n] = ||hp[h][n]||^2
// 64 rows per block, 256 threads, 4x4 register tiles.
// ---------------------------------------------------------------------------
__global__ void __launch_bounds__(256) k_proj(const float* __restrict__ x,
                                              const float* __restrict__ pw,
                                              const float* __restrict__ pb,
                                              const float* __restrict__ hw,
                                              const float* __restrict__ hb)
{
    __shared__ float As[64 * 68];   // x tile (then h tile), stride 68
    __shared__ float Ws[64 * 64];   // weight tile, stride 64

    const int tid = threadIdx.x;
    const int ty = tid >> 4, tx = tid & 15;
    const int row0 = blockIdx.x * 64;

    float acc[4][4];
#pragma unroll
    for (int i = 0; i < 4; i++)
#pragma unroll
        for (int j = 0; j < 4; j++) acc[i][j] = 0.f;

    for (int kk = 0; kk < D_IN; kk += 64) {
#pragma unroll
        for (int l = 0; l < 4; l++) {
            int idx = tid + l * 256;
            int r = idx >> 4;
            int c = (idx & 15) << 2;
            *(float4*)&As[r * 68 + c] = *(const float4*)&x[(size_t)(row0 + r) * D_IN + kk + c];
            *(float4*)&Ws[r * 64 + c] = *(const float4*)&pw[(size_t)(kk + r) * D_H + c];
        }
        __syncthreads();
#pragma unroll 8
        for (int k = 0; k < 64; k++) {
            float a0 = As[(4 * ty + 0) * 68 + k];
            float a1 = As[(4 * ty + 1) * 68 + k];
            float a2 = As[(4 * ty + 2) * 68 + k];
            float a3 = As[(4 * ty + 3) * 68 + k];
            float4 b = *(const float4*)&Ws[k * 64 + 4 * tx];
            acc[0][0] += a0 * b.x; acc[0][1] += a0 * b.y; acc[0][2] += a0 * b.z; acc[0][3] += a0 * b.w;
            acc[1][0] += a1 * b.x; acc[1][1] += a1 * b.y; acc[1][2] += a1 * b.z; acc[1][3] += a1 * b.w;
            acc[2][0] += a2 * b.x; acc[2][1] += a2 * b.y; acc[2][2] += a2 * b.z; acc[2][3] += a2 * b.w;
            acc[3][0] += a3 * b.x; acc[3][1] += a3 * b.y; acc[3][2] += a3 * b.z; acc[3][3] += a3 * b.w;
        }
        __syncthreads();
    }

    // bias + relu -> write h tile into As
    {
        float4 pbv = *(const float4*)&pb[4 * tx];
        float pbz[4] = {pbv.x, pbv.y, pbv.z, pbv.w};
#pragma unroll
        for (int i = 0; i < 4; i++)
#pragma unroll
            for (int j = 0; j < 4; j++)
                As[(4 * ty + i) * 68 + 4 * tx + j] = fmaxf(acc[i][j] + pbz[j], 0.f);
    }
    __syncthreads();

    for (int h = 0; h < N_HEADS; h++) {
#pragma unroll
        for (int l = 0; l < 4; l++) {
            int idx = tid + l * 256;
            int r = idx >> 4;
            int c = (idx & 15) << 2;
            *(float4*)&Ws[r * 64 + c] = *(const float4*)&hw[((size_t)h * 64 + r) * 64 + c];
        }
        __syncthreads();

        float a2c[4][4];
#pragma unroll
        for (int i = 0; i < 4; i++)
#pragma unroll
            for (int j = 0; j < 4; j++) a2c[i][j] = 0.f;

#pragma unroll 8
        for (int k = 0; k < 64; k++) {
            float a0 = As[(4 * ty + 0) * 68 + k];
            float a1 = As[(4 * ty + 1) * 68 + k];
            float a2 = As[(4 * ty + 2) * 68 + k];
            float a3 = As[(4 * ty + 3) * 68 + k];
            float4 b = *(const float4*)&Ws[k * 64 + 4 * tx];
            a2c[0][0] += a0 * b.x; a2c[0][1] += a0 * b.y; a2c[0][2] += a0 * b.z; a2c[0][3] += a0 * b.w;
            a2c[1][0] += a1 * b.x; a2c[1][1] += a1 * b.y; a2c[1][2] += a1 * b.z; a2c[1][3] += a1 * b.w;
            a2c[2][0] += a2 * b.x; a2c[2][1] += a2 * b.y; a2c[2][2] += a2 * b.z; a2c[2][3] += a2 * b.w;
            a2c[3][0] += a3 * b.x; a2c[3][1] += a3 * b.y; a2c[3][2] += a3 * b.z; a2c[3][3] += a3 * b.w;
        }

        float4 hbv = *(const float4*)&hb[h * 64 + 4 * tx];
        float hbz[4] = {hbv.x, hbv.y, hbv.z, hbv.w};
#pragma unroll
        for (int i = 0; i < 4; i++) {
            float v0 = a2c[i][0] + hbz[0];
            float v1 = a2c[i][1] + hbz[1];
            float v2 = a2c[i][2] + hbz[2];
            float v3 = a2c[i][3] + hbz[3];
            float rs = v0 * v0 + v1 * v1 + v2 * v2 + v3 * v3;
            *(float4*)&g_hp[((size_t)h * N_TOK + row0 + 4 * ty + i) * D_H + 4 * tx] =
                make_float4(v0, v1, v2, v3);
#pragma unroll
            for (int w = 1; w < 16; w <<= 1)
                rs += __shfl_xor_sync(0xffffffffu, rs, w, 16);
            if (tx == 0) g_ss[(size_t)h * N_TOK + row0 + 4 * ty + i] = rs;
        }
        __syncthreads();
    }
}

// ---------------------------------------------------------------------------
// Kernel 2: flash-attention style distance attention, per (head, 64-query block).
// S = -sqrt(max(qq + kk - 2 Q.K, 0)); online softmax; O += P@V.
// Q/K/P in smem transposed + XOR-swizzled (conflict-free LDS.128 on both frags).
// ---------------------------------------------------------------------------
__global__ void __launch_bounds__(256) k_attn()
{
    __shared__ float Qs[64 * 64];   // [d][row] swizzled
    __shared__ float KPs[64 * 64];  // K [d][key] swizzled, reused as P [key][row] swizzled
    __shared__ float Vs[64 * 64];   // [key][d] natural

    const int tid = threadIdx.x;
    const int ty = tid >> 4, tx = tid & 15;
    const int head = blockIdx.y;
    const int q0 = blockIdx.x * 64;
    const float* __restrict__ hp = g_hp + (size_t)head * (N_TOK * D_H);
    const float* __restrict__ ss = g_ss + (size_t)head * N_TOK;

    // Load Q transposed + swizzled (coalesced global reads: consecutive tid -> consecutive d)
#pragma unroll
    for (int l = 0; l < 16; l++) {
        int idx = tid + l * 256;   // 0..4095
        int d = idx & 63;
        int r = idx >> 6;
        Qs[d * 64 + ((((r >> 2) ^ (d & 15)) << 2) | (r & 3))] = hp[(size_t)(q0 + r) * D_H + d];
    }

    float qq[4];
#pragma unroll
    for (int i = 0; i < 4; i++) qq[i] = ss[q0 + 4 * ty + i];

    float m[4], lsum[4], O[4][4];
#pragma unroll
    for (int i = 0; i < 4; i++) {
        m[i] = -1e30f; lsum[i] = 0.f;
#pragma unroll
        for (int j = 0; j < 4; j++) O[i][j] = 0.f;
    }
    __syncthreads();

    for (int kt = 0; kt < N_TOK; kt += 64) {
        // K transposed + swizzled
#pragma unroll
        for (int l = 0; l < 16; l++) {
            int idx = tid + l * 256;
            int d = idx & 63;
            int r = idx >> 6;
            KPs[d * 64 + ((((r >> 2) ^ (d & 15)) << 2) | (r & 3))] = hp[(size_t)(kt + r) * D_H + d];
        }
        // V natural
#pragma unroll
        for (int l = 0; l < 4; l++) {
            int idx = tid + l * 256;
            int r = idx >> 4;
            int c = (idx & 15) << 2;
            *(float4*)&Vs[r * 64 + c] = *(const float4*)&hp[(size_t)(kt + r) * D_H + c];
        }
        __syncthreads();

        // S = Q.K^T
        float S[4][4];
#pragma unroll
        for (int i = 0; i < 4; i++)
#pragma unroll
            for (int j = 0; j < 4; j++) S[i][j] = 0.f;

#pragma unroll 8
        for (int k = 0; k < 64; k++) {
            float4 a = *(const float4*)&Qs[k * 64 + ((ty ^ (k & 15)) << 2)];
            float4 b = *(const float4*)&KPs[k * 64 + ((tx ^ (k & 15)) << 2)];
            S[0][0] += a.x * b.x; S[0][1] += a.x * b.y; S[0][2] += a.x * b.z; S[0][3] += a.x * b.w;
            S[1][0] += a.y * b.x; S[1][1] += a.y * b.y; S[1][2] += a.y * b.z; S[1][3] += a.y * b.w;
            S[2][0] += a.z * b.x; S[2][1] += a.z * b.y; S[2][2] += a.z * b.z; S[2][3] += a.z * b.w;
            S[3][0] += a.w * b.x; S[3][1] += a.w * b.y; S[3][2] += a.w * b.z; S[3][3] += a.w * b.w;
        }

        float4 kkv = *(const float4*)&ss[kt + 4 * tx];
        float kkz[4] = {kkv.x, kkv.y, kkv.z, kkv.w};

#pragma unroll
        for (int i = 0; i < 4; i++) {
            float best = -1e30f;
#pragma unroll
            for (int j = 0; j < 4; j++) {
                float sq = qq[i] + kkz[j] - 2.f * S[i][j];
                float s = (sq > 0.f) ? -sqrtf(sq) : 0.f;   // safe cdist (0 at 0)
                S[i][j] = s;
                best = fmaxf(best, s);
            }
#pragma unroll
            for (int w = 1; w < 16; w <<= 1)
                best = fmaxf(best, __shfl_xor_sync(0xffffffffu, best, w, 16));
            float newm = fmaxf(m[i], best);
            float scale = __expf(m[i] - newm);
            m[i] = newm;
            float rs = 0.f;
#pragma unroll
            for (int j = 0; j < 4; j++) {
                float p = __expf(S[i][j] - newm);
                S[i][j] = p;
                rs += p;
            }
#pragma unroll
            for (int w = 1; w < 16; w <<= 1)
                rs += __shfl_xor_sync(0xffffffffu, rs, w, 16);
            lsum[i] = lsum[i] * scale + rs;
#pragma unroll
            for (int c = 0; c < 4; c++) O[i][c] *= scale;
        }

        __syncthreads();   // everyone done reading KPs as K
        // Write P transposed + swizzled into KPs
#pragma unroll
        for (int i = 0; i < 4; i++) {
#pragma unroll
            for (int j = 0; j < 4; j++) {
                int col = 4 * tx + j;
                KPs[col * 64 + (((ty ^ (col & 15)) << 2) | i)] = S[i][j];
            }
        }
        __syncthreads();

        // O += P @ V
#pragma unroll 8
        for (int j = 0; j < 64; j++) {
            float4 a = *(const float4*)&KPs[j * 64 + ((ty ^ (j & 15)) << 2)];
            float4 b = *(const float4*)&Vs[j * 64 + 4 * tx];
            O[0][0] += a.x * b.x; O[0][1] += a.x * b.y; O[0][2] += a.x * b.z; O[0][3] += a.x * b.w;
            O[1][0] += a.y * b.x; O[1][1] += a.y * b.y; O[1][2] += a.y * b.z; O[1][3] += a.y * b.w;
            O[2][0] += a.z * b.x; O[2][1] += a.z * b.y; O[2][2] += a.z * b.z; O[2][3] += a.z * b.w;
            O[3][0] += a.w * b.x; O[3][1] += a.w * b.y; O[3][2] += a.w * b.z; O[3][3] += a.w * b.w;
        }
        __syncthreads();   // before next tile overwrites KPs/Vs
    }

#pragma unroll
    for (int i = 0; i < 4; i++) {
        float inv = 1.f / lsum[i];
        *(float4*)&g_hh[((size_t)head * N_TOK + q0 + 4 * ty + i) * D_H + 4 * tx] =
            make_float4(O[i][0] * inv, O[i][1] * inv, O[i][2] * inv, O[i][3] * inv);
    }
}

// ---------------------------------------------------------------------------
// Kernel 3: combine heads (softmax(attn_w) weights), LayerNorm(D_H=64), FC to 6.
// One warp per row; each lane owns dims {lane, lane+32}.
// ---------------------------------------------------------------------------
__global__ void __launch_bounds__(256) k_final(const float* __restrict__ attn_w,
                                               const float* __restrict__ gamma,
                                               const float* __restrict__ beta,
                                               const float* __restrict__ fcw,
                                               const float* __restrict__ fcb,
                                               float* __restrict__ out)
{
    const int warp = threadIdx.x >> 5;
    const int lane = threadIdx.x & 31;
    const int row = blockIdx.x * 8 + warp;

    float a0 = attn_w[0], a1 = attn_w[1], a2 = attn_w[2], a3 = attn_w[3];
    float mx = fmaxf(fmaxf(a0, a1), fmaxf(a2, a3));
    float aw[4];
    aw[0] = __expf(a0 - mx); aw[1] = __expf(a1 - mx);
    aw[2] = __expf(a2 - mx); aw[3] = __expf(a3 - mx);
    float ainv = 1.f / (aw[0] + aw[1] + aw[2] + aw[3]);

    const int d0 = lane, d1 = lane + 32;
    float c0 = 0.f, c1 = 0.f;
#pragma unroll
    for (int h = 0; h < N_HEADS; h++) {
        const float* p = g_hh + ((size_t)h * N_TOK + row) * D_H;
        c0 += aw[h] * p[d0];
        c1 += aw[h] * p[d1];
    }
    c0 *= ainv; c1 *= ainv;

    float s = c0 + c1;
#pragma unroll
    for (int w = 16; w; w >>= 1) s += __shfl_xor_sync(0xffffffffu, s, w);
    float mu = s * (1.f / 64.f);
    float v0 = c0 - mu, v1 = c1 - mu;
    float vv = v0 * v0 + v1 * v1;
#pragma unroll
    for (int w = 16; w; w >>= 1) vv += __shfl_xor_sync(0xffffffffu, vv, w);
    float inv = rsqrtf(vv * (1.f / 64.f) + LN_EPS);
    float n0 = v0 * inv * gamma[d0] + beta[d0];
    float n1 = v1 * inv * gamma[d1] + beta[d1];

    float o[N_CLS];
#pragma unroll
    for (int c = 0; c < N_CLS; c++)
        o[c] = n0 * fcw[d0 * N_CLS + c] + n1 * fcw[d1 * N_CLS + c];
#pragma unroll
    for (int c = 0; c < N_CLS; c++)
#pragma unroll
        for (int w = 16; w; w >>= 1) o[c] += __shfl_xor_sync(0xffffffffu, o[c], w);

    if (lane == 0) {
#pragma unroll
        for (int c = 0; c < N_CLS; c++)
            out[(size_t)row * N_CLS + c] = o[c] + fcb[c];
    }
}

// ---------------------------------------------------------------------------
extern "C" void kernel_launch(void* const* d_in, const int* in_sizes, int n_in,
                              void* d_out, int out_size)
{
    const float* x      = (const float*)d_in[0];
    const float* proj_w = (const float*)d_in[1];
    const float* proj_b = (const float*)d_in[2];
    const float* head_w = (const float*)d_in[3];
    const float* head_b = (const float*)d_in[4];
    const float* attn_w = (const float*)d_in[5];
    const float* gamma  = (const float*)d_in[6];
    const float* beta   = (const float*)d_in[7];
    const float* fc_w   = (const float*)d_in[8];
    const float* fc_b   = (const float*)d_in[9];
    float* out = (float*)d_out;

    k_proj<<<N_TOK / 64, 256>>>(x, proj_w, proj_b, head_w, head_b);

    dim3 g2(N_TOK / 64, N_HEADS);
    k_attn<<<g2, 256>>>();

    k_final<<<N_TOK / 8, 256>>>(attn_w, gamma, beta, fc_w, fc_b, out);
}